// round 4
// baseline (speedup 1.0000x reference)
#include <cuda_runtime.h>

#define BB    8
#define CC    16
#define HH    128
#define WW    128
#define PP    16384
#define KN    16
#define CK    144
#define IMG   (CC*HH*WW)      // 262144 = 2^18
#define NT    256
#define PADW  148             // wsm row stride (floats)
#define PADB  148             // patch row stride (floats); 4*PADB % 32 == 16 -> halves disjoint banks

// 8 MB scratch: x transposed to batch-innermost  x_t[i][b] = x[b][i]
__device__ __align__(32) float g_xt[IMG * BB];
// 1 if hash_idx buffer is int64 (high words all zero), 0 if int32
__device__ int g_idx_is64;

// ---- cp.async helpers (weights stream, L2 evict_first) ----
__device__ __forceinline__ void cp_async16_ef(void* smem_dst, const void* gptr) {
    unsigned s = (unsigned)__cvta_generic_to_shared(smem_dst);
    asm volatile(
        "{\n\t"
        ".reg .b64 pol;\n\t"
        "createpolicy.fractional.L2::evict_first.b64 pol, 1.0;\n\t"
        "cp.async.cg.shared.global.L2::cache_hint [%0], [%1], 16, pol;\n\t"
        "}\n"
        :: "r"(s), "l"(gptr) : "memory");
}
__device__ __forceinline__ void cp_async_commit_wait() {
    asm volatile("cp.async.commit_group;\n" ::: "memory");
    asm volatile("cp.async.wait_group 0;\n" ::: "memory");
}

// Transpose x [B][IMG] -> g_xt [IMG][B]; block 0 also probes idx dtype.
__global__ __launch_bounds__(NT) void transpose_kernel(
    const float* __restrict__ x, const unsigned* __restrict__ h32)
{
    if (blockIdx.x == 0 && threadIdx.x < 32) {
        unsigned v = h32[2u * (threadIdx.x * 36000u) + 1u];
        int all0 = __all_sync(0xFFFFFFFFu, v == 0u);
        if (threadIdx.x == 0) g_idx_is64 = all0;
    }
    int i = blockIdx.x * NT + threadIdx.x;
    float v[BB];
    #pragma unroll
    for (int b = 0; b < BB; b++)
        v[b] = __ldg(&x[b * IMG + i]);
    float4* dst = (float4*)&g_xt[(size_t)i * BB];
    dst[0] = make_float4(v[0], v[1], v[2], v[3]);
    dst[1] = make_float4(v[4], v[5], v[6], v[7]);
}

// One block = 2 pixels. Single barrier: gather (idx->x_t chain) runs while
// cp.async streams the weight tile; then everyone computes.
__global__ __launch_bounds__(NT, 8) void abc2d_kernel(
    const float* __restrict__ weights,
    const unsigned* __restrict__ hidx32,
    float* __restrict__ out)
{
    __shared__ __align__(16) float patchB[2][BB][PADB];  // [px][b][c]
    __shared__ __align__(16) float wsm[2][KN][PADW];     // [px][k][c]

    const int p2 = blockIdx.x;          // pixel pair
    const int t  = threadIdx.x;
    const int is64 = g_idx_is64;

    // ---- weights: 1152 float4 via cp.async, evict-first in L2 ----
    {
        const float4* wp = (const float4*)(weights + (size_t)(p2 * 2) * (KN * CK));
        #pragma unroll
        for (int r = 0; r < 4; r++) {
            int i = t + r * NT;                  // [0,1024)
            int pxw = i / 576;
            int j   = i - pxw * 576;
            int k   = j / 36;
            int c4  = j - k * 36;
            cp_async16_ef(&wsm[pxw][k][c4 * 4], &wp[i]);
        }
        if (t < 128) {
            int i = t + 1024;                    // [1024,1152)
            int j = i - 576;                     // pxw = 1
            int k = j / 36;
            int c4 = j - k * 36;
            cp_async16_ef(&wsm[1][k][c4 * 4], &wp[i]);
        }
    }

    // ---- gather: 576 lanes; idx load chains straight into x_t gather ----
    {
        #pragma unroll
        for (int r = 0; r < 3; r++) {
            int e = t + r * NT;
            if (r < 2 || t < 64) {               // 256+256+64 = 576
                int px   = (e >= 2 * CK) ? 1 : 0;
                int rem  = e - px * 2 * CK;
                int c    = rem >> 1;
                int half = rem & 1;
                int elem = (p2 * 2 + px) * CK + c;
                unsigned w = is64 ? __ldcs(&hidx32[2 * elem]) : __ldcs(&hidx32[elem]);
                int row = (int)(w & (IMG - 1));
                float4 v = __ldg((const float4*)&g_xt[(size_t)row * BB + half * 4]);
                int b0 = half * 4;
                patchB[px][b0 + 0][c] = v.x;
                patchB[px][b0 + 1][c] = v.y;
                patchB[px][b0 + 2][c] = v.z;
                patchB[px][b0 + 3][c] = v.w;
            }
        }
    }

    cp_async_commit_wait();
    __syncthreads();

    // ---- compute: t -> (px, k, b); pure LDS.128 pairs, broadcast-friendly ----
    {
        const int px = t >> 7;
        const int k  = (t >> 3) & 15;
        const int b  = t & 7;
        float acc = 0.f;
        #pragma unroll
        for (int c4 = 0; c4 < CK / 4; c4++) {
            float4 w4 = *(const float4*)&wsm[px][k][c4 * 4];
            float4 p4 = *(const float4*)&patchB[px][b][c4 * 4];
            acc += w4.x * p4.x;
            acc += w4.y * p4.y;
            acc += w4.z * p4.z;
            acc += w4.w * p4.w;
        }
        __stcs(&out[((b * KN + k) << 14) + p2 * 2 + px], acc);
    }
}

extern "C" void kernel_launch(void* const* d_in, const int* in_sizes, int n_in,
                              void* d_out, int out_size) {
    const float*    x   = (const float*)d_in[0];
    const float*    w   = (const float*)d_in[1];
    const unsigned* hid = (const unsigned*)d_in[2];
    float*          out = (float*)d_out;
    (void)in_sizes; (void)n_in; (void)out_size;

    transpose_kernel<<<IMG / NT, NT>>>(x, hid);
    abc2d_kernel<<<PP / 2, NT>>>(w, hid, out);
}

// round 5
// speedup vs baseline: 1.1876x; 1.1876x over previous
#include <cuda_runtime.h>

#define BB    8
#define CC    16
#define PP    16384
#define KN    16
#define CK    144
#define IMG   (CC*128*128)    // 262144 = 2^18
#define NT    256
#define NPX   4               // pixels per block
#define PAD   148             // row stride in floats (conflict-free pattern)

#define W_FLOATS   (NPX*KN*PAD)            // 9472
#define P_FLOATS   (NPX*BB*PAD)            // 4736
#define SMEM_BYTES ((W_FLOATS + P_FLOATS)*4)  // 56832

// 8 MB scratch: x transposed to batch-innermost  x_t[i][b] = x[b][i]
__device__ __align__(32) float g_xt[IMG * BB];
// 1 if hash_idx buffer is int64 (high words all zero), 0 if int32
__device__ int g_idx_is64;

__device__ __forceinline__ void cp_async16_ef(void* smem_dst, const void* gptr) {
    unsigned s = (unsigned)__cvta_generic_to_shared(smem_dst);
    asm volatile(
        "{\n\t"
        ".reg .b64 pol;\n\t"
        "createpolicy.fractional.L2::evict_first.b64 pol, 1.0;\n\t"
        "cp.async.cg.shared.global.L2::cache_hint [%0], [%1], 16, pol;\n\t"
        "}\n"
        :: "r"(s), "l"(gptr) : "memory");
}
__device__ __forceinline__ void cp_async_commit_wait() {
    asm volatile("cp.async.commit_group;\n" ::: "memory");
    asm volatile("cp.async.wait_group 0;\n" ::: "memory");
}

// Transpose x [B][IMG] -> g_xt [IMG][B]; block 0 also probes idx dtype.
__global__ __launch_bounds__(NT) void transpose_kernel(
    const float* __restrict__ x, const unsigned* __restrict__ h32)
{
    if (blockIdx.x == 0 && threadIdx.x < 32) {
        unsigned v = h32[2u * (threadIdx.x * 36000u) + 1u];
        int all0 = __all_sync(0xFFFFFFFFu, v == 0u);
        if (threadIdx.x == 0) g_idx_is64 = all0;
    }
    int i = blockIdx.x * NT + threadIdx.x;
    float v[BB];
    #pragma unroll
    for (int b = 0; b < BB; b++)
        v[b] = __ldg(&x[b * IMG + i]);
    float4* dst = (float4*)&g_xt[(size_t)i * BB];
    dst[0] = make_float4(v[0], v[1], v[2], v[3]);
    dst[1] = make_float4(v[4], v[5], v[6], v[7]);
}

__global__ __launch_bounds__(NT, 4) void abc2d_kernel(
    const float* __restrict__ weights,
    const unsigned* __restrict__ hidx32,
    float* __restrict__ out)
{
    extern __shared__ __align__(16) float smem[];
    float* wsm   = smem;              // [NPX][KN][PAD]
    float* patch = smem + W_FLOATS;   // [NPX][BB][PAD]  (reused as outsm later)

    const int p0 = blockIdx.x * NPX;
    const int t  = threadIdx.x;
    const int is64 = g_idx_is64;

    // ---- weights: 2304 float4 via cp.async, evict-first (overlaps gather) ----
    {
        const float4* wp = (const float4*)(weights + (size_t)p0 * (KN * CK));
        #pragma unroll
        for (int r = 0; r < 9; r++) {
            int i  = t + r * NT;              // [0,2304)
            int px = i / 576;
            int j  = i - px * 576;
            int k  = j / 36;
            int c4 = j - k * 36;
            cp_async16_ef(&wsm[(px * KN + k) * PAD + c4 * 4], &wp[i]);
        }
    }

    // ---- gather: 1152 lanes; idx load chains into x_t float4 gather ----
    {
        #pragma unroll
        for (int r = 0; r < 5; r++) {
            int e = t + r * NT;
            if (r < 4 || t < (NPX * 2 * CK - 4 * NT)) {   // 1024 + 128
                int px   = e / (2 * CK);
                int rem  = e - px * (2 * CK);
                int c    = rem >> 1;
                int half = rem & 1;
                int elem = (p0 + px) * CK + c;
                unsigned w = is64 ? __ldcs(&hidx32[2 * elem]) : __ldcs(&hidx32[elem]);
                int row = (int)(w & (IMG - 1));
                float4 v = __ldg((const float4*)&g_xt[(size_t)row * BB + half * 4]);
                int b0 = half * 4;
                float* pr = &patch[(px * BB + b0) * PAD + c];
                pr[0 * PAD] = v.x;
                pr[1 * PAD] = v.y;
                pr[2 * PAD] = v.z;
                pr[3 * PAD] = v.w;
            }
        }
    }

    cp_async_commit_wait();
    __syncthreads();

    // ---- compute: t -> (px, k2, b); 2 k-rows per thread ----
    const int px = t >> 6;
    const int k2 = (t >> 3) & 7;
    const int b  = t & 7;
    const int k0 = k2 * 2;
    float acc0 = 0.f, acc1 = 0.f;
    {
        const float* wr0 = &wsm[(px * KN + k0) * PAD];
        const float* wr1 = wr0 + PAD;
        const float* pr  = &patch[(px * BB + b) * PAD];
        #pragma unroll
        for (int c4 = 0; c4 < CK / 4; c4++) {
            float4 p4 = *(const float4*)&pr[c4 * 4];
            float4 wa = *(const float4*)&wr0[c4 * 4];
            float4 wb = *(const float4*)&wr1[c4 * 4];
            acc0 += wa.x * p4.x; acc0 += wa.y * p4.y;
            acc0 += wa.z * p4.z; acc0 += wa.w * p4.w;
            acc1 += wb.x * p4.x; acc1 += wb.y * p4.y;
            acc1 += wb.z * p4.z; acc1 += wb.w * p4.w;
        }
    }

    // ---- staged output: outsm[(b*16+k)][px], then STG.128 of 4 contiguous p ----
    __syncthreads();                       // all patch reads done; reuse as outsm
    float* outsm = patch;                  // needs 128*4 floats
    outsm[((b << 4) + k0) * NPX + px]     = acc0;
    outsm[((b << 4) + k0 + 1) * NPX + px] = acc1;
    __syncthreads();

    if (t < KN * BB) {
        float4 v = *(const float4*)&outsm[t * NPX];
        __stcs((float4*)&out[((size_t)t << 14) + p0], v);
    }
}

extern "C" void kernel_launch(void* const* d_in, const int* in_sizes, int n_in,
                              void* d_out, int out_size) {
    const float*    x   = (const float*)d_in[0];
    const float*    w   = (const float*)d_in[1];
    const unsigned* hid = (const unsigned*)d_in[2];
    float*          out = (float*)d_out;
    (void)in_sizes; (void)n_in; (void)out_size;

    cudaFuncSetAttribute(abc2d_kernel,
                         cudaFuncAttributeMaxDynamicSharedMemorySize, SMEM_BYTES);
    transpose_kernel<<<IMG / NT, NT>>>(x, hid);
    abc2d_kernel<<<PP / NPX, NT, SMEM_BYTES>>>(w, hid, out);
}

// round 6
// speedup vs baseline: 1.3867x; 1.1677x over previous
#include <cuda_runtime.h>
#include <cstdint>

#define BB    8
#define PP    16384
#define KN    16
#define CK    144
#define IMG   (16*128*128)    // 262144 = 2^18
#define NT    256
#define NPX   4               // pixels per block
#define PADP  148             // patch row stride (floats)

#define W_FLOATS   (NPX*KN*CK)            // 9216 (36864 B, raw bulk-copy layout)
#define P_FLOATS   (NPX*BB*PADP)          // 4736
#define SMEM_BYTES ((W_FLOATS + P_FLOATS)*4 + 16)

// 8 MB scratch: x transposed to batch-innermost  x_t[i][b] = x[b][i]
__device__ __align__(32) float g_xt[IMG * BB];
__device__ int g_idx_is64;

// Transpose x [B][IMG] -> g_xt [IMG][B]; block 0 probes idx dtype.
__global__ __launch_bounds__(NT) void transpose_kernel(
    const float* __restrict__ x, const unsigned* __restrict__ h32)
{
    if (blockIdx.x == 0 && threadIdx.x < 32) {
        unsigned v = h32[2u * (threadIdx.x * 36000u) + 1u];
        int all0 = __all_sync(0xFFFFFFFFu, v == 0u);
        if (threadIdx.x == 0) g_idx_is64 = all0;
    }
    int i = blockIdx.x * NT + threadIdx.x;
    float v[BB];
    #pragma unroll
    for (int b = 0; b < BB; b++)
        v[b] = __ldg(&x[b * IMG + i]);
    float4* dst = (float4*)&g_xt[(size_t)i * BB];
    dst[0] = make_float4(v[0], v[1], v[2], v[3]);
    dst[1] = make_float4(v[4], v[5], v[6], v[7]);
}

__global__ __launch_bounds__(NT, 4) void abc2d_kernel(
    const float* __restrict__ weights,
    const unsigned* __restrict__ hidx32,
    float* __restrict__ out)
{
    extern __shared__ __align__(16) float smem[];
    float* wsm   = smem;                          // [NPX][KN][CK] raw
    float* patch = smem + W_FLOATS;               // [NPX][BB][PADP]
    unsigned mbar = (unsigned)__cvta_generic_to_shared(smem + W_FLOATS + P_FLOATS);

    const int p0 = blockIdx.x * NPX;
    const int t  = threadIdx.x;
    const int is64 = g_idx_is64;

    if (t == 0)
        asm volatile("mbarrier.init.shared.b64 [%0], 1;" :: "r"(mbar) : "memory");
    __syncthreads();

    // ---- weights: ONE bulk copy (36864 B contiguous), evict-first in L2 ----
    if (t == 0) {
        unsigned d = (unsigned)__cvta_generic_to_shared(wsm);
        const float* src = weights + (size_t)p0 * (KN * CK);
        asm volatile("mbarrier.arrive.expect_tx.shared.b64 _, [%0], %1;"
                     :: "r"(mbar), "r"(W_FLOATS * 4) : "memory");
        asm volatile(
            "{\n\t"
            ".reg .b64 pol;\n\t"
            "createpolicy.fractional.L2::evict_first.b64 pol, 1.0;\n\t"
            "cp.async.bulk.shared::cluster.global.mbarrier::complete_tx::bytes.L2::cache_hint"
            " [%0], [%1], %2, [%3], pol;\n\t"
            "}\n"
            :: "r"(d), "l"(src), "r"(W_FLOATS * 4), "r"(mbar) : "memory");
    }

    // ---- gather (overlaps the bulk copy): 1152 lanes, idx -> x_t float4 ----
    {
        #pragma unroll
        for (int r = 0; r < 5; r++) {
            int e = t + r * NT;
            if (r < 4 || t < (NPX * 2 * CK - 4 * NT)) {   // 1024 + 128
                int px   = e / (2 * CK);
                int rem  = e - px * (2 * CK);
                int c    = rem >> 1;
                int half = rem & 1;
                int elem = (p0 + px) * CK + c;
                unsigned w = is64 ? __ldcs(&hidx32[2 * elem]) : __ldcs(&hidx32[elem]);
                int row = (int)(w & (IMG - 1));
                float4 v = __ldg((const float4*)&g_xt[(size_t)row * BB + half * 4]);
                int b0 = half * 4;
                float* pr = &patch[(px * BB + b0) * PADP + c];
                pr[0 * PADP] = v.x;
                pr[1 * PADP] = v.y;
                pr[2 * PADP] = v.z;
                pr[3 * PADP] = v.w;
            }
        }
    }

    __syncthreads();          // patch writes visible

    // wait for the weight bulk copy
    asm volatile(
        "{\n\t"
        ".reg .pred P1;\n\t"
        "WL_%=:\n\t"
        "mbarrier.try_wait.parity.acquire.cta.shared::cta.b64 P1, [%0], 0, 0x989680;\n\t"
        "@P1 bra.uni WD_%=;\n\t"
        "bra.uni WL_%=;\n\t"
        "WD_%=:\n\t"
        "}\n"
        :: "r"(mbar) : "memory");

    // ---- compute: 128 threads; thread = (px, kq, b), 4 k-rows each.
    //      kq-staggered c4 schedule -> w reads conflict-free, p at 4-phase floor.
    float acc0 = 0.f, acc1 = 0.f, acc2 = 0.f, acc3 = 0.f;
    const int px = t >> 5;
    const int kq = (t >> 3) & 3;
    const int b  = t & 7;
    if (t < 128) {
        const float* wr = wsm + (px * KN + kq * 4) * CK;
        const float* pr = patch + (px * BB + b) * PADP;
        const int a0 = kq * 9;
        #pragma unroll 6
        for (int j = 0; j < 36; j++) {
            int a = a0 + j;
            if (a >= 36) a -= 36;
            float4 p4 = *(const float4*)&pr[a * 4];
            float4 w0 = *(const float4*)&wr[0 * CK + a * 4];
            float4 w1 = *(const float4*)&wr[1 * CK + a * 4];
            float4 w2 = *(const float4*)&wr[2 * CK + a * 4];
            float4 w3 = *(const float4*)&wr[3 * CK + a * 4];
            acc0 += w0.x * p4.x; acc0 += w0.y * p4.y; acc0 += w0.z * p4.z; acc0 += w0.w * p4.w;
            acc1 += w1.x * p4.x; acc1 += w1.y * p4.y; acc1 += w1.z * p4.z; acc1 += w1.w * p4.w;
            acc2 += w2.x * p4.x; acc2 += w2.y * p4.y; acc2 += w2.z * p4.z; acc2 += w2.w * p4.w;
            acc3 += w3.x * p4.x; acc3 += w3.y * p4.y; acc3 += w3.z * p4.z; acc3 += w3.w * p4.w;
        }
    }

    // ---- staged output: outsm[(b*16+k)][px], then STG.128 of 4 contiguous p ----
    __syncthreads();                        // patch reads done; reuse as outsm
    float* outsm = patch;                   // 128*NPX floats
    if (t < 128) {
        int r = b * KN + kq * 4;
        outsm[(r + 0) * NPX + px] = acc0;
        outsm[(r + 1) * NPX + px] = acc1;
        outsm[(r + 2) * NPX + px] = acc2;
        outsm[(r + 3) * NPX + px] = acc3;
    }
    __syncthreads();

    if (t < KN * BB) {
        float4 v = *(const float4*)&outsm[t * NPX];
        __stcs((float4*)&out[((size_t)t << 14) + p0], v);
    }
}

extern "C" void kernel_launch(void* const* d_in, const int* in_sizes, int n_in,
                              void* d_out, int out_size) {
    const float*    x   = (const float*)d_in[0];
    const float*    w   = (const float*)d_in[1];
    const unsigned* hid = (const unsigned*)d_in[2];
    float*          out = (float*)d_out;
    (void)in_sizes; (void)n_in; (void)out_size;

    cudaFuncSetAttribute(abc2d_kernel,
                         cudaFuncAttributeMaxDynamicSharedMemorySize, SMEM_BYTES);
    transpose_kernel<<<IMG / NT, NT>>>(x, hid);
    abc2d_kernel<<<PP / NPX, NT, SMEM_BYTES>>>(w, hid, out);
}

// round 7
// speedup vs baseline: 1.5232x; 1.0985x over previous
#include <cuda_runtime.h>
#include <cuda_fp16.h>

#define BB    8
#define PP    16384
#define KN    16
#define CK    144
#define IMG   (16*128*128)    // 262144 = 2^18
#define NT    256
#define NPX   4               // pixels per block
#define PADP  148             // patch row stride (floats); quad perm 5b+s conflict-free
#define WSTRIDE 2312          // per-px weight tile stride in floats (2304+8); %32==8

#define W_FLOATS  (NPX*WSTRIDE)           // 9248
#define P_FLOATS  (NPX*BB*PADP)           // 4736
#define SMEM_BYTES ((W_FLOATS + P_FLOATS)*4 + 16)

// 4 MB scratch: x transposed + fp16-packed, batch-innermost (row = 16B)
__device__ __align__(16) __half g_xth[IMG * BB];
__device__ int g_idx_is64;

__device__ __forceinline__ void fma2(unsigned long long& d,
                                     unsigned long long a, unsigned long long b) {
    asm("fma.rn.f32x2 %0, %1, %2, %0;" : "+l"(d) : "l"(a), "l"(b));
}

// Transpose+pack x [B][IMG] -> g_xth [IMG][B] (fp16); block 0 probes idx dtype.
__global__ __launch_bounds__(NT) void transpose_kernel(
    const float* __restrict__ x, const unsigned* __restrict__ h32)
{
    if (blockIdx.x == 0 && threadIdx.x < 32) {
        unsigned v = h32[2u * (threadIdx.x * 36000u) + 1u];
        int all0 = __all_sync(0xFFFFFFFFu, v == 0u);
        if (threadIdx.x == 0) g_idx_is64 = all0;
    }
    int i = blockIdx.x * NT + threadIdx.x;
    __half2 h[4];
    #pragma unroll
    for (int q = 0; q < 4; q++) {
        float lo = __ldg(&x[(2 * q) * IMG + i]);
        float hi = __ldg(&x[(2 * q + 1) * IMG + i]);
        h[q] = __floats2half2_rn(lo, hi);
    }
    *(uint4*)&g_xth[(size_t)i * BB] = *(uint4*)h;
}

__global__ __launch_bounds__(NT, 4) void abc2d_kernel(
    const float* __restrict__ weights,
    const unsigned* __restrict__ hidx32,
    float* __restrict__ out)
{
    extern __shared__ __align__(16) float smem[];
    float* wsm   = smem;                          // [NPX][WSTRIDE] (2304 used + 8 pad)
    float* patch = smem + W_FLOATS;               // [NPX*BB][PADP]
    unsigned mbar = (unsigned)__cvta_generic_to_shared(smem + W_FLOATS + P_FLOATS);

    const int p0 = blockIdx.x * NPX;
    const int t  = threadIdx.x;
    const int is64 = g_idx_is64;

    if (t == 0)
        asm volatile("mbarrier.init.shared.b64 [%0], 1;" :: "r"(mbar) : "memory");
    __syncthreads();

    // ---- weights: 4 bulk copies (9216 B each) into px-padded tiles ----
    if (t == 0) {
        asm volatile("mbarrier.arrive.expect_tx.shared.b64 _, [%0], %1;"
                     :: "r"(mbar), "r"(NPX * KN * CK * 4) : "memory");
        #pragma unroll
        for (int px = 0; px < NPX; px++) {
            unsigned d = (unsigned)__cvta_generic_to_shared(wsm + px * WSTRIDE);
            const float* src = weights + (size_t)(p0 + px) * (KN * CK);
            asm volatile(
                "{\n\t"
                ".reg .b64 pol;\n\t"
                "createpolicy.fractional.L2::evict_first.b64 pol, 1.0;\n\t"
                "cp.async.bulk.shared::cluster.global.mbarrier::complete_tx::bytes.L2::cache_hint"
                " [%0], [%1], %2, [%3], pol;\n\t"
                "}\n"
                :: "r"(d), "l"(src), "r"(KN * CK * 4), "r"(mbar) : "memory");
        }
    }

    // ---- gather (overlaps copy): 576 LDG.128 lanes, one per (px,c) ----
    {
        #pragma unroll
        for (int r = 0; r < 3; r++) {
            int e = t + r * NT;
            if (r < 2 || t < (NPX * CK - 2 * NT)) {   // 512 + 64
                int px = e / CK;
                int c  = e - px * CK;
                int elem = (p0 + px) * CK + c;
                unsigned w = is64 ? __ldcs(&hidx32[2 * elem]) : __ldcs(&hidx32[elem]);
                int row = (int)(w & (IMG - 1));
                uint4 hv = __ldg((const uint4*)&g_xth[(size_t)row * BB]);
                __half2* hp = (__half2*)&hv;
                float* pr = &patch[(px * BB) * PADP + c];
                #pragma unroll
                for (int q = 0; q < 4; q++) {
                    float2 f = __half22float2(hp[q]);
                    pr[(2 * q) * PADP]     = f.x;
                    pr[(2 * q + 1) * PADP] = f.y;
                }
            }
        }
    }

    __syncthreads();          // patch writes visible

    // wait for the weight bulk copies
    asm volatile(
        "{\n\t"
        ".reg .pred P1;\n\t"
        "WL_%=:\n\t"
        "mbarrier.try_wait.parity.acquire.cta.shared::cta.b64 P1, [%0], 0, 0x989680;\n\t"
        "@P1 bra.uni WD_%=;\n\t"
        "bra.uni WL_%=;\n\t"
        "WD_%=:\n\t"
        "}\n"
        :: "r"(mbar) : "memory");

    // ---- compute: warps 0-3; warp = (px-pair, k-octet); lane = (s, px_lo, b).
    //      s = j-parity split; each lane does 18 c4-steps, 8 k-rows, f32x2 FMA.
    int px = 0, b = 0, k0 = 0, s = 0;
    float res[8];
    if (t < 128) {
        const int wid  = t >> 5;
        const int lane = t & 31;
        s = lane >> 4;
        const int px_lo = (lane >> 3) & 1;
        b  = lane & 7;
        px = (wid & 1) * 2 + px_lo;
        k0 = (wid >> 1) * 8;

        unsigned long long acc[8];
        #pragma unroll
        for (int k = 0; k < 8; k++) acc[k] = 0ull;

        const float* wr = wsm + px * WSTRIDE + k0 * CK;
        const float* pr = patch + (px * BB + b) * PADP;
        #pragma unroll
        for (int jj = 0; jj < 18; jj++) {
            const float* pa = &pr[(jj * 2 + s) * 4];
            ulonglong2 p2 = *(const ulonglong2*)pa;
            #pragma unroll
            for (int k = 0; k < 8; k++) {
                ulonglong2 w2 = *(const ulonglong2*)&wr[k * CK + (jj * 2 + s) * 4];
                fma2(acc[k], p2.x, w2.x);
                fma2(acc[k], p2.y, w2.y);
            }
        }
        #pragma unroll
        for (int k = 0; k < 8; k++) {
            float lo = __uint_as_float((unsigned)acc[k]);
            float hi = __uint_as_float((unsigned)(acc[k] >> 32));
            res[k] = lo + hi;
            res[k] += __shfl_xor_sync(0xFFFFFFFFu, res[k], 16);
        }
    }

    // ---- staged output: outsm[b][k][px] stride 68 (conflict-free), STG.128 ----
    __syncthreads();                        // patch reads done; reuse as outsm
    float* outsm = patch;                   // 8*68 = 544 floats
    if (t < 128 && s == 0) {
        int base = b * 68 + k0 * 4 + px;
        #pragma unroll
        for (int k = 0; k < 8; k++)
            outsm[base + k * 4] = res[k];
    }
    __syncthreads();

    if (t < KN * BB) {
        int bb = t >> 4, kk = t & 15;
        float4 v = *(const float4*)&outsm[bb * 68 + kk * 4];
        __stcs((float4*)&out[((size_t)t << 14) + p0], v);
    }
}

extern "C" void kernel_launch(void* const* d_in, const int* in_sizes, int n_in,
                              void* d_out, int out_size) {
    const float*    x   = (const float*)d_in[0];
    const float*    w   = (const float*)d_in[1];
    const unsigned* hid = (const unsigned*)d_in[2];
    float*          out = (float*)d_out;
    (void)in_sizes; (void)n_in; (void)out_size;

    cudaFuncSetAttribute(abc2d_kernel,
                         cudaFuncAttributeMaxDynamicSharedMemorySize, SMEM_BYTES);
    transpose_kernel<<<IMG / NT, NT>>>(x, hid);
    abc2d_kernel<<<PP / NPX, NT, SMEM_BYTES>>>(w, hid, out);
}